// round 8
// baseline (speedup 1.0000x reference)
#include <cuda_runtime.h>
#include <cuda_bf16.h>

// Problem constants (fixed shapes from reference):
//   x:    (4, 64, 512, 512) fp32
//   iperm:(4, 4) int32
//   out:  (4, 64, 256, 256) fp32
//
// out[b, n*4+k, h, w] = sum_g x[b, g*16+n, 2h + pos/2, 2w + pos%2], pos = iperm[g*4+k]
//
// FINAL configuration. 7-round experiment matrix (kernel us / DRAM%):
//   R1 plain/plain, cap:   47.8-49.1 / 81.6-83.6   (noise band)
//   R2 4-wide tile (spill):60.4 / 71.1
//   R3 cs/cs no cap:       48.2 / 80.4 (occ 65%)
//   R4 cs/cs + cap:        48.1 / 80.3  <- best scored dur_us (51.1)
//   R5 persistent 1-wave:  49.7 / 80.2
//   R7 plain/cs + cap:     48.6 / 81.8
// The op saturates the chip-wide LTS service cap (~7 TB/s effective app
// traffic through L2, reads+writes, each byte moved exactly once, fully
// coalesced). No kernel-side lever moves it further; compute/issue <30%.

__device__ __forceinline__ float sel4(float v0, float v1, float v2, float v3, int pos) {
    float a = (pos & 1) ? v1 : v0;   // pos in {0,1}
    float b = (pos & 1) ? v3 : v2;   // pos in {2,3}
    return (pos & 2) ? b : a;
}

__global__ void __launch_bounds__(256, 8)
muxout_transpose_kernel(const float* __restrict__ x,
                        const int*   __restrict__ iperm,
                        float*       __restrict__ out) {
    __shared__ int sp[16];
    if (threadIdx.x < 16) sp[threadIdx.x] = iperm[threadIdx.x];
    __syncthreads();

    // Total threads: B(4) * Ng(16) * H(256) * W/2(128) = 2,097,152
    const unsigned t  = blockIdx.x * 256u + threadIdx.x;
    const int w2 = t & 127;          // 0..127  (covers output w = 2*w2, 2*w2+1)
    const int h  = (t >> 7) & 255;   // 0..255
    const int n  = (t >> 15) & 15;   // 0..15
    const int b  = t >> 19;          // 0..3

    float acc_lo[4] = {0.f, 0.f, 0.f, 0.f};
    float acc_hi[4] = {0.f, 0.f, 0.f, 0.f};

    #pragma unroll
    for (int g = 0; g < 4; g++) {
        const size_t chan = (size_t)(b * 64 + g * 16 + n);
        const float4* row0 = reinterpret_cast<const float4*>(
            x + (chan * 512 + (size_t)(2 * h)) * 512) + w2;
        const float4* row1 = row0 + 128;  // next input row (+512 floats)
        const float4 r0 = __ldcs(row0);
        const float4 r1 = __ldcs(row1);
        // pos = sh*2 + sw; lo = output col 2*w2, hi = 2*w2+1
        #pragma unroll
        for (int k = 0; k < 4; k++) {
            const int pos = sp[g * 4 + k];
            acc_lo[k] += sel4(r0.x, r0.y, r1.x, r1.y, pos);
            acc_hi[k] += sel4(r0.z, r0.w, r1.z, r1.w, pos);
        }
    }

    const size_t out_base = (((size_t)(b * 64 + n * 4)) * 256 + h) * 256 + 2 * w2;

    #pragma unroll
    for (int k = 0; k < 4; k++) {
        float2 o; o.x = acc_lo[k]; o.y = acc_hi[k];
        __stcs(reinterpret_cast<float2*>(out + out_base + (size_t)k * (256 * 256)), o);
    }
}

extern "C" void kernel_launch(void* const* d_in, const int* in_sizes, int n_in,
                              void* d_out, int out_size) {
    const float* x     = (const float*)d_in[0];
    const int*   iperm = (const int*)d_in[1];
    float*       out   = (float*)d_out;

    muxout_transpose_kernel<<<8192, 256>>>(x, iperm, out);
}

// round 9
// speedup vs baseline: 1.0137x; 1.0137x over previous
#include <cuda_runtime.h>
#include <cuda_bf16.h>

// Problem constants (fixed shapes from reference):
//   x:    (4, 64, 512, 512) fp32
//   iperm:(4, 4) int32
//   out:  (4, 64, 256, 256) fp32
//
// out[b, n*4+k, h, w] = sum_g x[b, g*16+n, 2h + pos/2, 2w + pos%2], pos = iperm[g*4+k]
//
// CONVERGED FINAL. 8-round experiment matrix (kernel us / DRAM%):
//   R1/R6 plain/plain+cap: 47.8-49.1 / 81.6-83.6
//   R2 4-wide tile (spill):60.4 / 71.1
//   R3 cs/cs no cap:       48.2 / 80.4 (occ 65%)
//   R4/R8 cs/cs + cap:     47.4-48.1 / 80.3-81.6  <- best scored (51.1) and
//                                                    best kernel time (47.36)
//   R5 persistent 1-wave:  49.7 / 80.2
//   R7 plain/cs + cap:     48.6 / 81.8
// Identical-source reruns show +-0.9us scored noise; all variants are one
// noise band. The op saturates the chip-wide LTS service cap (~7.1 TB/s
// effective app traffic, reads+writes, each byte moved exactly once, fully
// coalesced; LTS cap is path-independent so TMA cannot beat it). Compute,
// issue, L1, occupancy all have >50% headroom -- memory-roofline-final.

__device__ __forceinline__ float sel4(float v0, float v1, float v2, float v3, int pos) {
    float a = (pos & 1) ? v1 : v0;   // pos in {0,1}
    float b = (pos & 1) ? v3 : v2;   // pos in {2,3}
    return (pos & 2) ? b : a;
}

__global__ void __launch_bounds__(256, 8)
muxout_transpose_kernel(const float* __restrict__ x,
                        const int*   __restrict__ iperm,
                        float*       __restrict__ out) {
    __shared__ int sp[16];
    if (threadIdx.x < 16) sp[threadIdx.x] = iperm[threadIdx.x];
    __syncthreads();

    // Total threads: B(4) * Ng(16) * H(256) * W/2(128) = 2,097,152
    const unsigned t  = blockIdx.x * 256u + threadIdx.x;
    const int w2 = t & 127;          // 0..127  (covers output w = 2*w2, 2*w2+1)
    const int h  = (t >> 7) & 255;   // 0..255
    const int n  = (t >> 15) & 15;   // 0..15
    const int b  = t >> 19;          // 0..3

    float acc_lo[4] = {0.f, 0.f, 0.f, 0.f};
    float acc_hi[4] = {0.f, 0.f, 0.f, 0.f};

    #pragma unroll
    for (int g = 0; g < 4; g++) {
        const size_t chan = (size_t)(b * 64 + g * 16 + n);
        const float4* row0 = reinterpret_cast<const float4*>(
            x + (chan * 512 + (size_t)(2 * h)) * 512) + w2;
        const float4* row1 = row0 + 128;  // next input row (+512 floats)
        const float4 r0 = __ldcs(row0);
        const float4 r1 = __ldcs(row1);
        // pos = sh*2 + sw; lo = output col 2*w2, hi = 2*w2+1
        #pragma unroll
        for (int k = 0; k < 4; k++) {
            const int pos = sp[g * 4 + k];
            acc_lo[k] += sel4(r0.x, r0.y, r1.x, r1.y, pos);
            acc_hi[k] += sel4(r0.z, r0.w, r1.z, r1.w, pos);
        }
    }

    const size_t out_base = (((size_t)(b * 64 + n * 4)) * 256 + h) * 256 + 2 * w2;

    #pragma unroll
    for (int k = 0; k < 4; k++) {
        float2 o; o.x = acc_lo[k]; o.y = acc_hi[k];
        __stcs(reinterpret_cast<float2*>(out + out_base + (size_t)k * (256 * 256)), o);
    }
}

extern "C" void kernel_launch(void* const* d_in, const int* in_sizes, int n_in,
                              void* d_out, int out_size) {
    const float* x     = (const float*)d_in[0];
    const int*   iperm = (const int*)d_in[1];
    float*       out   = (float*)d_out;

    muxout_transpose_kernel<<<8192, 256>>>(x, iperm, out);
}